// round 12
// baseline (speedup 1.0000x reference)
#include <cuda_runtime.h>
#include <math.h>
#include <stdint.h>

static constexpr int SEQ    = 2048;
static constexpr int DMODEL = 768;
static constexpr int NHEAD  = 12;
static constexpr int HDIM   = 64;

// ---------------------------------------------------------------------------
// Scratch (no allocations allowed -> __device__ globals)
// ---------------------------------------------------------------------------
__device__ float g_xr [SEQ * DMODEL];           // tf32-rounded x
__device__ float g_wr [3 * DMODEL * DMODEL];    // tf32-rounded [Wq;Wk;Wv]
__device__ float g_wpr[DMODEL * DMODEL];        // tf32-rounded Wp
__device__ float g_q [SEQ * DMODEL];            // x @ Wq^T   (fp32)
__device__ float g_k [SEQ * DMODEL];            // x @ Wk^T
__device__ float g_v [SEQ * DMODEL];            // x @ Wv^T
// Q/K rows (d-dim) and V/P t-dim are PAIR-PERMUTED within 8-element groups:
//   sp(c) = c<4 ? 2c : 2c-7  -> elements (t4, t4+4) sit adjacent -> LDS.64.
__device__ float g_qb[NHEAD * SEQ * HDIM];      // normed+rope+scaled Q, [h][t][perm d]
__device__ float g_kb[NHEAD * SEQ * HDIM];      // normed+rope K, [h][t][perm d]
__device__ float g_vt[NHEAD * HDIM * SEQ];      // blended V^T, [h][d][perm t]
__device__ float g_ob[SEQ * DMODEL];            // attention output, [t][h*64+d], tf32

// ---------------------------------------------------------------------------
// Helpers
// ---------------------------------------------------------------------------
__device__ __forceinline__ float to_tf32(float x) {
    uint32_t u;
    asm("cvt.rna.tf32.f32 %0, %1;" : "=r"(u) : "f"(x));
    return __uint_as_float(u);
}

__device__ __forceinline__ int sp8(int c) {   // pair-permute within 8
    return (c < 4) ? (2 * c) : (2 * c - 7);
}

__device__ __forceinline__ uint32_t smem_u32(const void* p) {
    uint32_t a;
    asm("{ .reg .u64 t; cvta.to.shared.u64 t, %1; cvt.u32.u64 %0, t; }"
        : "=r"(a) : "l"(p));
    return a;
}

__device__ __forceinline__ void cp_async16(uint32_t s, const void* g) {
    asm volatile("cp.async.cg.shared.global [%0], [%1], 16;" :: "r"(s), "l"(g));
}
__device__ __forceinline__ void cp_commit() {
    asm volatile("cp.async.commit_group;" ::: "memory");
}
template <int N>
__device__ __forceinline__ void cp_wait() {
    asm volatile("cp.async.wait_group %0;" :: "n"(N) : "memory");
}

// D += A * B : m16n8k8 tf32 mma. a: 4 regs, b: 2 regs, d: 4 f32.
__device__ __forceinline__ void mma8(float* d, const float* a, const float* b) {
    asm volatile(
        "mma.sync.aligned.m16n8k8.row.col.f32.tf32.tf32.f32 "
        "{%0,%1,%2,%3}, {%4,%5,%6,%7}, {%8,%9}, {%0,%1,%2,%3};\n"
        : "+f"(d[0]), "+f"(d[1]), "+f"(d[2]), "+f"(d[3])
        : "r"(__float_as_uint(a[0])), "r"(__float_as_uint(a[1])),
          "r"(__float_as_uint(a[2])), "r"(__float_as_uint(a[3])),
          "r"(__float_as_uint(b[0])), "r"(__float_as_uint(b[1])));
}

__device__ __forceinline__ float red_max4(float v) {
    v = fmaxf(v, __shfl_xor_sync(0xffffffffu, v, 1));
    v = fmaxf(v, __shfl_xor_sync(0xffffffffu, v, 2));
    return v;
}
__device__ __forceinline__ float red_sum4(float v) {
    v += __shfl_xor_sync(0xffffffffu, v, 1);
    v += __shfl_xor_sync(0xffffffffu, v, 2);
    return v;
}

// ---------------------------------------------------------------------------
// Kernel 0: rna-tf32 pre-round of x and all weights (one float4 per thread)
// ---------------------------------------------------------------------------
__global__ void __launch_bounds__(256)
round_kernel(const float* __restrict__ x,  const float* __restrict__ wq,
             const float* __restrict__ wk, const float* __restrict__ wv,
             const float* __restrict__ wp)
{
    int i = blockIdx.x * 256 + threadIdx.x;  // float4 index, total 983040
    const float* src;
    float* dst;
    int off;
    if (i < 393216)       { src = x;  dst = g_xr;           off = i; }
    else if (i < 540672)  { src = wq; dst = g_wr;           off = i - 393216; }
    else if (i < 688128)  { src = wk; dst = g_wr + 589824;  off = i - 540672; }
    else if (i < 835584)  { src = wv; dst = g_wr + 1179648; off = i - 688128; }
    else                  { src = wp; dst = g_wpr;          off = i - 835584; }
    float4 v = ((const float4*)src)[off];
    v.x = to_tf32(v.x); v.y = to_tf32(v.y);
    v.z = to_tf32(v.z); v.w = to_tf32(v.w);
    ((float4*)dst)[off] = v;
}

// ---------------------------------------------------------------------------
// Templated tf32 mma.sync GEMM core: C[BM x BN] tile of A[*,768] @ B[*,768]^T.
// 3-stage cp.async pipeline, ONE __syncthreads per K-chunk.
// ---------------------------------------------------------------------------
template <int BM, int BN, int WGM, int WGN>
__device__ __forceinline__ void gemm_mma_core(const float* __restrict__ A,
                                              const float* __restrict__ B,
                                              float* __restrict__ C, int ldc)
{
    constexpr int MT = BM / WGM / 16;
    constexpr int NT = BN / WGN / 8;
    constexpr int NKT = DMODEL / 32;
    constexpr int ACH = BM / 32;
    constexpr int BCH = BN / 32;

    extern __shared__ float sm[];
    const uint32_t sb = smem_u32(sm);
    const uint32_t bBase = (uint32_t)(3 * BM * 36 * 4);

    const int tid  = threadIdx.x;
    const int warp = tid >> 5, lane = tid & 31;
    const int wm = warp % WGM, wn = warp / WGM;
    const int g  = lane >> 2, t4 = lane & 3;

    float acc[MT][NT][4];
#pragma unroll
    for (int i = 0; i < MT; i++)
#pragma unroll
        for (int j = 0; j < NT; j++)
#pragma unroll
            for (int e = 0; e < 4; e++) acc[i][j][e] = 0.f;

    auto issue = [&](int buf, int kt) {
        const uint32_t aO = (uint32_t)(buf * BM * 36 * 4);
        const uint32_t bO = bBase + (uint32_t)(buf * BN * 36 * 4);
        const float* ga = A + kt * 32;
#pragma unroll
        for (int v = 0; v < ACH; v++) {
            int idx = tid + v * 256, r = idx >> 3, c4 = idx & 7;
            cp_async16(sb + aO + (uint32_t)(r * 144 + c4 * 16),
                       ga + r * DMODEL + c4 * 4);
        }
        const float* gb = B + kt * 32;
#pragma unroll
        for (int v = 0; v < BCH; v++) {
            int idx = tid + v * 256, r = idx >> 3, c4 = idx & 7;
            cp_async16(sb + bO + (uint32_t)(r * 144 + c4 * 16),
                       gb + r * DMODEL + c4 * 4);
        }
        cp_commit();
    };

    issue(0, 0);
    issue(1, 1);

    for (int kt = 0; kt < NKT; kt++) {
        if (kt + 1 < NKT) cp_wait<1>();
        else              cp_wait<0>();
        __syncthreads();                    // chunk kt ready; all warps past kt-1
        if (kt + 2 < NKT) issue((kt + 2) % 3, kt + 2);

        const int buf = kt % 3;
        const float (*As)[36] = (const float(*)[36])(sm + buf * BM * 36);
        const float (*Bs)[36] = (const float(*)[36])(sm + 3 * BM * 36 + buf * BN * 36);

#pragma unroll
        for (int kk = 0; kk < 4; kk++) {
            float af[MT][4], bf[NT][2];
#pragma unroll
            for (int mt = 0; mt < MT; mt++) {
                int r = wm * (BM / WGM) + mt * 16 + g;
                af[mt][0] = As[r    ][kk * 8 + t4];
                af[mt][1] = As[r + 8][kk * 8 + t4];
                af[mt][2] = As[r    ][kk * 8 + t4 + 4];
                af[mt][3] = As[r + 8][kk * 8 + t4 + 4];
            }
#pragma unroll
            for (int nt = 0; nt < NT; nt++) {
                int c = wn * (BN / WGN) + nt * 8 + g;
                bf[nt][0] = Bs[c][kk * 8 + t4];
                bf[nt][1] = Bs[c][kk * 8 + t4 + 4];
            }
#pragma unroll
            for (int mt = 0; mt < MT; mt++)
#pragma unroll
                for (int nt = 0; nt < NT; nt++)
                    mma8(acc[mt][nt], af[mt], bf[nt]);
        }
    }
    __syncthreads();

#pragma unroll
    for (int mt = 0; mt < MT; mt++) {
        int r0 = wm * (BM / WGM) + mt * 16 + g;
#pragma unroll
        for (int nt = 0; nt < NT; nt++) {
            int c0 = wn * (BN / WGN) + nt * 8 + 2 * t4;
            *(float2*)(C + r0 * ldc + c0)       = make_float2(acc[mt][nt][0], acc[mt][nt][1]);
            *(float2*)(C + (r0 + 8) * ldc + c0) = make_float2(acc[mt][nt][2], acc[mt][nt][3]);
        }
    }
}

static constexpr int QKV_SMEM  = 3 * (128 + 128) * 36 * 4;  // 110592
static constexpr int PROJ_SMEM = 3 * (128 +  64) * 36 * 4;  // 82944

// Kernel 1: fused QKV projection. grid (16, 18)
__global__ void __launch_bounds__(256, 2)
gemm_qkv_k()
{
    int bm = blockIdx.x;
    int nb = blockIdx.y;
    int sel = nb / 6, bn = nb % 6;
    float* Cbase = (sel == 0) ? g_q : (sel == 1) ? g_k : g_v;
    gemm_mma_core<128, 128, 2, 4>(g_xr + bm * 128 * DMODEL,
                                  g_wr + nb * 128 * DMODEL,
                                  Cbase + bm * 128 * DMODEL + bn * 128, DMODEL);
}

// Kernel 4: output projection. grid (16, 12)
__global__ void __launch_bounds__(256, 2)
gemm_proj_k(float* __restrict__ out)
{
    gemm_mma_core<128, 64, 4, 2>(g_ob + blockIdx.x * 128 * DMODEL,
                                 g_wpr + blockIdx.y * 64 * DMODEL,
                                 out + blockIdx.x * 128 * DMODEL + blockIdx.y * 64,
                                 DMODEL);
}

// ---------------------------------------------------------------------------
// Kernel 2: V blend + RMS-norm(q,k) + RoPE + pair-permuted layout writes.
// grid (12, 64)
// ---------------------------------------------------------------------------
__global__ void __launch_bounds__(256)
epilogue_kernel(const float* __restrict__ vi, const float* __restrict__ lambp)
{
    const int h  = blockIdx.x;
    const int t0 = blockIdx.y * 32;
    const int tid = threadIdx.x, warp = tid >> 5, lane = tid & 31;
    const float lamb = *lambp;

    __shared__ float vsh[64][33];

    const float invf = powf(1e-4f, (float)lane * (1.0f / 32.0f));
    // pair-permuted position of d = lane within its 8-group; d+32 -> +32.
    const int pb = (lane & ~7) + sp8(lane & 7);

#pragma unroll
    for (int it = 0; it < 4; it++) {
        const int tl = warp * 4 + it;
        const int t  = t0 + tl;
        const int base = t * DMODEL + h * 64 + lane;

        float q1 = g_q[base], q2 = g_q[base + 32];
        float k1 = g_k[base], k2 = g_k[base + 32];
        float v1 = g_v[base], v2 = g_v[base + 32];
        float w1 = vi[base],  w2 = vi[base + 32];
        v1 = (1.f - lamb) * v1 + lamb * w1;
        v2 = (1.f - lamb) * v2 + lamb * w2;

        float sq = q1 * q1 + q2 * q2;
        float sk = k1 * k1 + k2 * k2;
#pragma unroll
        for (int m = 16; m; m >>= 1) {
            sq += __shfl_xor_sync(0xffffffffu, sq, m);
            sk += __shfl_xor_sync(0xffffffffu, sk, m);
        }
        const float rq = rsqrtf(sq * (1.f / 64.f) + 1.1920929e-7f);
        const float rk = rsqrtf(sk * (1.f / 64.f) + 1.1920929e-7f);
        q1 *= rq; q2 *= rq; k1 *= rk; k2 *= rk;

        const float ang = (float)t * invf;
        float s, c;
        sincosf(ang, &s, &c);
        float qa =  q1 * c + q2 * s;
        float qb = -q1 * s + q2 * c;
        float ka =  k1 * c + k2 * s;
        float kb = -k1 * s + k2 * c;

        qa *= 0.125f; qb *= 0.125f;

        const int ob = (h * SEQ + t) * 64;
        g_qb[ob + pb]      = to_tf32(qa);
        g_qb[ob + pb + 32] = to_tf32(qb);
        g_kb[ob + pb]      = to_tf32(ka);
        g_kb[ob + pb + 32] = to_tf32(kb);

        vsh[lane][tl]      = to_tf32(v1);
        vsh[lane + 32][tl] = to_tf32(v2);
    }
    __syncthreads();

    // write V transposed [h][d][perm t]
#pragma unroll
    for (int v = 0; v < 8; v++) {
        int idx = tid + v * 256;
        int d = idx >> 5, tl = idx & 31;
        int tp = (tl & ~7) + sp8(tl & 7);
        g_vt[(h * 64 + d) * SEQ + t0 + tp] = vsh[d][tl];
    }
}

// ---------------------------------------------------------------------------
// Kernel 3: causal flash attention, in-CTA KV split + pair-permuted fragments.
// grid (32, 12), 256 threads = 8 warps; all mma operand feeds are LDS.64.
// smem 87,040 B -> 2 CTAs/SM.
// ---------------------------------------------------------------------------
__global__ void __launch_bounds__(256, 2)
attn_kernel()
{
    extern __shared__ float sm_attn[];
    constexpr int TS = 64 * 68;
    float (*qs)[68] = (float(*)[68])(sm_attn);

    const int tid  = threadIdx.x;
    const int warp = tid >> 5, lane = tid & 31;
    const int half = warp >> 2, w = warp & 3;
    const int htid = tid & 127;

    float (*ks)[68] = (float(*)[68])(sm_attn + (1 + 2 * half) * TS);
    float (*vs)[68] = (float(*)[68])(sm_attn + (2 + 2 * half) * TS);
    float (*ps)[68] = ks;                     // alias: P overwrites consumed K
    const uint32_t qsb = smem_u32(sm_attn);
    const uint32_t ksb = smem_u32(&ks[0][0]);
    const uint32_t vsb = smem_u32(&vs[0][0]);
    // merge exchange buffers live in half-0's (dead-by-then) K/V regions
    float* xo  = sm_attn + 1 * TS;            // [128][33] floats
    float* xml = sm_attn + 2 * TS;            // [128][4]  floats

    const int bx = blockIdx.x;
    const int qt = (bx & 1) ? (bx >> 1) : (31 - (bx >> 1));
    const int h  = blockIdx.y;
    const int g = lane >> 2, t4 = lane & 3;

    const int nj  = qt + 1;
    const int c0  = nj >> 1;
    const int jlo = half ? c0 : 0;
    const int jhi = half ? nj : c0;

    const float* qg = g_qb + (h * SEQ + qt * 64) * 64;
    const float* kh = g_kb + h * SEQ * 64;
    const float* vh = g_vt + (h * 64) * SEQ;

    auto issue_kv = [&](int jt) {
#pragma unroll
        for (int v = 0; v < 8; v++) {
            int idx = htid + v * 128;
            int r = idx >> 4, c4 = idx & 15;
            cp_async16(ksb + (uint32_t)(r * 272 + c4 * 16),
                       kh + (jt * 64 + r) * 64 + c4 * 4);
            cp_async16(vsb + (uint32_t)(r * 272 + c4 * 16),
                       vh + r * SEQ + jt * 64 + c4 * 4);
        }
        cp_commit();
    };
    auto barh = [&]() {
        asm volatile("bar.sync %0, 128;" :: "r"(1 + half) : "memory");
    };

    // initial: Q (all 256 threads) + this half's first K/V
#pragma unroll
    for (int v = 0; v < 4; v++) {
        int idx = tid + v * 256;
        int r = idx >> 4, c4 = idx & 15;
        cp_async16(qsb + (uint32_t)(r * 272 + c4 * 16), qg + r * 64 + c4 * 4);
    }
    if (jhi > jlo) issue_kv(jlo);
    else           cp_commit();
    cp_wait<0>();
    __syncthreads();

    float o[8][4];
#pragma unroll
    for (int nt = 0; nt < 8; nt++)
#pragma unroll
        for (int e = 0; e < 4; e++) o[nt][e] = 0.f;
    float m0 = -INFINITY, m1 = -INFINITY, l0 = 0.f, l1 = 0.f;

    const int r0 = w * 16 + g;
    // permuted P store positions (pos of col 2*t4 and 2*t4+1 within 8-group)
    const int pp0 = sp8(2 * t4);
    const int pp1 = sp8(2 * t4 + 1);

    for (int jt = jlo; jt < jhi; jt++) {
        if (jt > jlo) cp_wait<0>();
        barh();

        // ---- S = Q K^T  (all fragment feeds are LDS.64 pairs) ----
        float s[8][4];
#pragma unroll
        for (int nt = 0; nt < 8; nt++)
#pragma unroll
            for (int e = 0; e < 4; e++) s[nt][e] = 0.f;
#pragma unroll
        for (int kk = 0; kk < 8; kk++) {
            float af[4];
            {
                float2 qa = *(const float2*)&qs[r0    ][kk * 8 + 2 * t4];
                float2 qc = *(const float2*)&qs[r0 + 8][kk * 8 + 2 * t4];
                af[0] = qa.x; af[1] = qc.x; af[2] = qa.y; af[3] = qc.y;
            }
#pragma unroll
            for (int nt = 0; nt < 8; nt++) {
                float2 kp = *(const float2*)&ks[nt * 8 + g][kk * 8 + 2 * t4];
                float bf[2] = {kp.x, kp.y};
                mma8(s[nt], af, bf);
            }
        }
        barh();                     // half done reading ks (P will overwrite)

        // ---- causal mask (diagonal tile; reachable only in upper half) ----
        if (jt == qt) {
#pragma unroll
            for (int nt = 0; nt < 8; nt++) {
                int cc = nt * 8 + 2 * t4;
                if (cc     > r0    ) s[nt][0] = -1e30f;
                if (cc + 1 > r0    ) s[nt][1] = -1e30f;
                if (cc     > r0 + 8) s[nt][2] = -1e30f;
                if (cc + 1 > r0 + 8) s[nt][3] = -1e30f;
            }
        }

        // ---- online softmax ----
        float mx0 = -INFINITY, mx1 = -INFINITY;
#pragma unroll
        for (int nt = 0; nt < 8; nt++) {
            mx0 = fmaxf(mx0, fmaxf(s[nt][0], s[nt][1]));
            mx1 = fmaxf(mx1, fmaxf(s[nt][2], s[nt][3]));
        }
        mx0 = red_max4(mx0);
        mx1 = red_max4(mx1);
        const float mn0 = fmaxf(m0, mx0), mn1 = fmaxf(m1, mx1);
        const float a0 = __expf(m0 - mn0), a1 = __expf(m1 - mn1);

        float rs0 = 0.f, rs1 = 0.f;
#pragma unroll
        for (int nt = 0; nt < 8; nt++) {
            s[nt][0] = __expf(s[nt][0] - mn0);
            s[nt][1] = __expf(s[nt][1] - mn0);
            s[nt][2] = __expf(s[nt][2] - mn1);
            s[nt][3] = __expf(s[nt][3] - mn1);
            rs0 += s[nt][0] + s[nt][1];
            rs1 += s[nt][2] + s[nt][3];
        }
        rs0 = red_sum4(rs0);
        rs1 = red_sum4(rs1);
        l0 = l0 * a0 + rs0;
        l1 = l1 * a1 + rs1;
#pragma unroll
        for (int nt = 0; nt < 8; nt++) {
            o[nt][0] *= a0; o[nt][1] *= a0;
            o[nt][2] *= a1; o[nt][3] *= a1;
        }
        m0 = mn0; m1 = mn1;

        // ---- P into (dead) K buffer, pair-permuted t positions ----
#pragma unroll
        for (int nt = 0; nt < 8; nt++) {
            ps[r0    ][nt * 8 + pp0] = to_tf32(s[nt][0]);
            ps[r0    ][nt * 8 + pp1] = to_tf32(s[nt][1]);
            ps[r0 + 8][nt * 8 + pp0] = to_tf32(s[nt][2]);
            ps[r0 + 8][nt * 8 + pp1] = to_tf32(s[nt][3]);
        }
        __syncwarp();

        // ---- O += P @ V  (LDS.64 feeds) ----
#pragma unroll
        for (int kk = 0; kk < 8; kk++) {
            float af[4];
            {
                float2 pa = *(const float2*)&ps[r0    ][kk * 8 + 2 * t4];
                float2 pc = *(const float2*)&ps[r0 + 8][kk * 8 + 2 * t4];
                af[0] = pa.x; af[1] = pc.x; af[2] = pa.y; af[3] = pc.y;
            }
#pragma unroll
            for (int nt = 0; nt < 8; nt++) {
                float2 vp = *(const float2*)&vs[nt * 8 + g][kk * 8 + 2 * t4];
                float bf[2] = {vp.x, vp.y};
                mma8(o[nt], af, bf);
            }
        }
        barh();                     // done with vs + ps before next load
        if (jt + 1 < jhi) issue_kv(jt + 1);
    }

    // ---- merge halves (exact split-softmax recombination) ----
    if (half == 0) {
#pragma unroll
        for (int nt = 0; nt < 8; nt++) {
#pragma unroll
            for (int e = 0; e < 4; e++)
                xo[htid * 33 + nt * 4 + e] = o[nt][e];
        }
        xml[htid * 4 + 0] = m0;
        xml[htid * 4 + 1] = m1;
        xml[htid * 4 + 2] = l0;
        xml[htid * 4 + 3] = l1;
    }
    __syncthreads();
    if (half == 1) {
        const float mA0 = xml[htid * 4 + 0], mA1 = xml[htid * 4 + 1];
        const float lA0 = xml[htid * 4 + 2], lA1 = xml[htid * 4 + 3];
        const float ms0 = fmaxf(m0, mA0), ms1 = fmaxf(m1, mA1);
        const float aa0 = __expf(mA0 - ms0), bb0 = __expf(m0 - ms0);
        const float aa1 = __expf(mA1 - ms1), bb1 = __expf(m1 - ms1);
        const float il0 = 1.f / (aa0 * lA0 + bb0 * l0);
        const float il1 = 1.f / (aa1 * lA1 + bb1 * l1);

        const int tr0 = qt * 64 + r0;
#pragma unroll
        for (int nt = 0; nt < 8; nt++) {
            const float* xp = xo + htid * 33 + nt * 4;
            int col = h * 64 + nt * 8 + 2 * t4;
            float v0 = (aa0 * xp[0] + bb0 * o[nt][0]) * il0;
            float v1 = (aa0 * xp[1] + bb0 * o[nt][1]) * il0;
            float v2 = (aa1 * xp[2] + bb1 * o[nt][2]) * il1;
            float v3 = (aa1 * xp[3] + bb1 * o[nt][3]) * il1;
            *(float2*)(g_ob + tr0 * DMODEL + col) =
                make_float2(to_tf32(v0), to_tf32(v1));
            *(float2*)(g_ob + (tr0 + 8) * DMODEL + col) =
                make_float2(to_tf32(v2), to_tf32(v3));
        }
    }
}

// ---------------------------------------------------------------------------
// Launch
// ---------------------------------------------------------------------------
extern "C" void kernel_launch(void* const* d_in, const int* in_sizes, int n_in,
                              void* d_out, int out_size)
{
    (void)in_sizes; (void)n_in; (void)out_size;
    const float* x    = (const float*)d_in[0];
    const float* vi   = (const float*)d_in[1];
    const float* Wq   = (const float*)d_in[2];
    const float* Wk   = (const float*)d_in[3];
    const float* Wv   = (const float*)d_in[4];
    const float* Wp   = (const float*)d_in[5];
    const float* lamb = (const float*)d_in[6];

    cudaFuncSetAttribute(gemm_qkv_k,
                         cudaFuncAttributeMaxDynamicSharedMemorySize, QKV_SMEM);
    cudaFuncSetAttribute(gemm_proj_k,
                         cudaFuncAttributeMaxDynamicSharedMemorySize, PROJ_SMEM);

    round_kernel<<<3840, 256>>>(x, Wq, Wk, Wv, Wp);
    gemm_qkv_k<<<dim3(16, 18), 256, QKV_SMEM>>>();
    epilogue_kernel<<<dim3(12, 64), 256>>>(vi, lamb);

    const int attn_smem = 5 * 64 * 68 * (int)sizeof(float);  // 87040 B
    cudaFuncSetAttribute(attn_kernel, cudaFuncAttributeMaxDynamicSharedMemorySize,
                         attn_smem);
    attn_kernel<<<dim3(32, 12), 256, attn_smem>>>();

    gemm_proj_k<<<dim3(16, 12), 256, PROJ_SMEM>>>((float*)d_out);
}

// round 14
// speedup vs baseline: 1.1518x; 1.1518x over previous
#include <cuda_runtime.h>
#include <math.h>
#include <stdint.h>

static constexpr int SEQ    = 2048;
static constexpr int DMODEL = 768;
static constexpr int NHEAD  = 12;
static constexpr int HDIM   = 64;

// ---------------------------------------------------------------------------
// Scratch (no allocations allowed -> __device__ globals)
// ---------------------------------------------------------------------------
__device__ float g_xr [SEQ * DMODEL];           // tf32-rounded x
__device__ float g_wr [3 * DMODEL * DMODEL];    // tf32-rounded [Wq;Wk;Wv]
__device__ float g_wpr[DMODEL * DMODEL];        // tf32-rounded Wp
__device__ float g_q [SEQ * DMODEL];            // x @ Wq^T   (fp32)
__device__ float g_k [SEQ * DMODEL];            // x @ Wk^T
__device__ float g_v [SEQ * DMODEL];            // x @ Wv^T
__device__ float g_qb[NHEAD * SEQ * HDIM];      // normed+rope+scaled Q, [h][t][d], tf32
__device__ float g_kb[NHEAD * SEQ * HDIM];      // normed+rope K, [h][t][d], tf32
__device__ float g_vt[NHEAD * HDIM * SEQ];      // blended V^T, [h][d][t], tf32
__device__ float g_ob[SEQ * DMODEL];            // attention output, [t][h*64+d], tf32

// ---------------------------------------------------------------------------
// Helpers
// ---------------------------------------------------------------------------
__device__ __forceinline__ float to_tf32(float x) {
    uint32_t u;
    asm("cvt.rna.tf32.f32 %0, %1;" : "=r"(u) : "f"(x));
    return __uint_as_float(u);
}

__device__ __forceinline__ uint32_t smem_u32(const void* p) {
    uint32_t a;
    asm("{ .reg .u64 t; cvta.to.shared.u64 t, %1; cvt.u32.u64 %0, t; }"
        : "=r"(a) : "l"(p));
    return a;
}

__device__ __forceinline__ void cp_async16(uint32_t s, const void* g) {
    asm volatile("cp.async.cg.shared.global [%0], [%1], 16;" :: "r"(s), "l"(g));
}
__device__ __forceinline__ void cp_commit() {
    asm volatile("cp.async.commit_group;" ::: "memory");
}
template <int N>
__device__ __forceinline__ void cp_wait() {
    asm volatile("cp.async.wait_group %0;" :: "n"(N) : "memory");
}

// D += A * B : m16n8k8 tf32 mma. a: 4 regs, b: 2 regs, d: 4 f32.
__device__ __forceinline__ void mma8(float* d, const float* a, const float* b) {
    asm volatile(
        "mma.sync.aligned.m16n8k8.row.col.f32.tf32.tf32.f32 "
        "{%0,%1,%2,%3}, {%4,%5,%6,%7}, {%8,%9}, {%0,%1,%2,%3};\n"
        : "+f"(d[0]), "+f"(d[1]), "+f"(d[2]), "+f"(d[3])
        : "r"(__float_as_uint(a[0])), "r"(__float_as_uint(a[1])),
          "r"(__float_as_uint(a[2])), "r"(__float_as_uint(a[3])),
          "r"(__float_as_uint(b[0])), "r"(__float_as_uint(b[1])));
}

__device__ __forceinline__ float red_max4(float v) {
    v = fmaxf(v, __shfl_xor_sync(0xffffffffu, v, 1));
    v = fmaxf(v, __shfl_xor_sync(0xffffffffu, v, 2));
    return v;
}
__device__ __forceinline__ float red_sum4(float v) {
    v += __shfl_xor_sync(0xffffffffu, v, 1);
    v += __shfl_xor_sync(0xffffffffu, v, 2);
    return v;
}

// ---------------------------------------------------------------------------
// Kernel 0: rna-tf32 pre-round of x and all weights (one float4 per thread)
// ---------------------------------------------------------------------------
__global__ void __launch_bounds__(256)
round_kernel(const float* __restrict__ x,  const float* __restrict__ wq,
             const float* __restrict__ wk, const float* __restrict__ wv,
             const float* __restrict__ wp)
{
    int i = blockIdx.x * 256 + threadIdx.x;  // float4 index, total 983040
    const float* src;
    float* dst;
    int off;
    if (i < 393216)       { src = x;  dst = g_xr;           off = i; }
    else if (i < 540672)  { src = wq; dst = g_wr;           off = i - 393216; }
    else if (i < 688128)  { src = wk; dst = g_wr + 589824;  off = i - 540672; }
    else if (i < 835584)  { src = wv; dst = g_wr + 1179648; off = i - 688128; }
    else                  { src = wp; dst = g_wpr;          off = i - 835584; }
    float4 v = ((const float4*)src)[off];
    v.x = to_tf32(v.x); v.y = to_tf32(v.y);
    v.z = to_tf32(v.z); v.w = to_tf32(v.w);
    ((float4*)dst)[off] = v;
}

// ---------------------------------------------------------------------------
// Templated tf32 mma.sync GEMM core: C[BM x BN] tile of A[*,768] @ B[*,768]^T.
// 3-stage cp.async pipeline, ONE __syncthreads per K-chunk (proven R11 win).
// ---------------------------------------------------------------------------
template <int BM, int BN, int WGM, int WGN>
__device__ __forceinline__ void gemm_mma_core(const float* __restrict__ A,
                                              const float* __restrict__ B,
                                              float* __restrict__ C, int ldc)
{
    constexpr int MT = BM / WGM / 16;
    constexpr int NT = BN / WGN / 8;
    constexpr int NKT = DMODEL / 32;
    constexpr int ACH = BM / 32;
    constexpr int BCH = BN / 32;

    extern __shared__ float sm[];
    const uint32_t sb = smem_u32(sm);
    const uint32_t bBase = (uint32_t)(3 * BM * 36 * 4);

    const int tid  = threadIdx.x;
    const int warp = tid >> 5, lane = tid & 31;
    const int wm = warp % WGM, wn = warp / WGM;
    const int g  = lane >> 2, t4 = lane & 3;

    float acc[MT][NT][4];
#pragma unroll
    for (int i = 0; i < MT; i++)
#pragma unroll
        for (int j = 0; j < NT; j++)
#pragma unroll
            for (int e = 0; e < 4; e++) acc[i][j][e] = 0.f;

    auto issue = [&](int buf, int kt) {
        const uint32_t aO = (uint32_t)(buf * BM * 36 * 4);
        const uint32_t bO = bBase + (uint32_t)(buf * BN * 36 * 4);
        const float* ga = A + kt * 32;
#pragma unroll
        for (int v = 0; v < ACH; v++) {
            int idx = tid + v * 256, r = idx >> 3, c4 = idx & 7;
            cp_async16(sb + aO + (uint32_t)(r * 144 + c4 * 16),
                       ga + r * DMODEL + c4 * 4);
        }
        const float* gb = B + kt * 32;
#pragma unroll
        for (int v = 0; v < BCH; v++) {
            int idx = tid + v * 256, r = idx >> 3, c4 = idx & 7;
            cp_async16(sb + bO + (uint32_t)(r * 144 + c4 * 16),
                       gb + r * DMODEL + c4 * 4);
        }
        cp_commit();
    };

    issue(0, 0);
    issue(1, 1);

    for (int kt = 0; kt < NKT; kt++) {
        if (kt + 1 < NKT) cp_wait<1>();
        else              cp_wait<0>();
        __syncthreads();                    // chunk kt ready; all warps past kt-1
        if (kt + 2 < NKT) issue((kt + 2) % 3, kt + 2);

        const int buf = kt % 3;
        const float (*As)[36] = (const float(*)[36])(sm + buf * BM * 36);
        const float (*Bs)[36] = (const float(*)[36])(sm + 3 * BM * 36 + buf * BN * 36);

#pragma unroll
        for (int kk = 0; kk < 4; kk++) {
            float af[MT][4], bf[NT][2];
#pragma unroll
            for (int mt = 0; mt < MT; mt++) {
                int r = wm * (BM / WGM) + mt * 16 + g;
                af[mt][0] = As[r    ][kk * 8 + t4];
                af[mt][1] = As[r + 8][kk * 8 + t4];
                af[mt][2] = As[r    ][kk * 8 + t4 + 4];
                af[mt][3] = As[r + 8][kk * 8 + t4 + 4];
            }
#pragma unroll
            for (int nt = 0; nt < NT; nt++) {
                int c = wn * (BN / WGN) + nt * 8 + g;
                bf[nt][0] = Bs[c][kk * 8 + t4];
                bf[nt][1] = Bs[c][kk * 8 + t4 + 4];
            }
#pragma unroll
            for (int mt = 0; mt < MT; mt++)
#pragma unroll
                for (int nt = 0; nt < NT; nt++)
                    mma8(acc[mt][nt], af[mt], bf[nt]);
        }
    }
    __syncthreads();

#pragma unroll
    for (int mt = 0; mt < MT; mt++) {
        int r0 = wm * (BM / WGM) + mt * 16 + g;
#pragma unroll
        for (int nt = 0; nt < NT; nt++) {
            int c0 = wn * (BN / WGN) + nt * 8 + 2 * t4;
            *(float2*)(C + r0 * ldc + c0)       = make_float2(acc[mt][nt][0], acc[mt][nt][1]);
            *(float2*)(C + (r0 + 8) * ldc + c0) = make_float2(acc[mt][nt][2], acc[mt][nt][3]);
        }
    }
}

static constexpr int QKV_SMEM  = 3 * (128 + 128) * 36 * 4;  // 110592
static constexpr int PROJ_SMEM = 3 * (128 +  64) * 36 * 4;  // 82944

// Kernel 1: fused QKV projection. grid (16, 18)
__global__ void __launch_bounds__(256, 2)
gemm_qkv_k()
{
    int bm = blockIdx.x;
    int nb = blockIdx.y;
    int sel = nb / 6, bn = nb % 6;
    float* Cbase = (sel == 0) ? g_q : (sel == 1) ? g_k : g_v;
    gemm_mma_core<128, 128, 2, 4>(g_xr + bm * 128 * DMODEL,
                                  g_wr + nb * 128 * DMODEL,
                                  Cbase + bm * 128 * DMODEL + bn * 128, DMODEL);
}

// Kernel 4: output projection. grid (16, 12)
__global__ void __launch_bounds__(256, 2)
gemm_proj_k(float* __restrict__ out)
{
    gemm_mma_core<128, 64, 4, 2>(g_ob + blockIdx.x * 128 * DMODEL,
                                 g_wpr + blockIdx.y * 64 * DMODEL,
                                 out + blockIdx.x * 128 * DMODEL + blockIdx.y * 64,
                                 DMODEL);
}

// ---------------------------------------------------------------------------
// Kernel 2: V blend + RMS-norm(q,k) + RoPE + layout shuffles.  grid (12, 64)
// (R9 layout: NO fragment permutation — scalar LDS proved fastest.)
// ---------------------------------------------------------------------------
__global__ void __launch_bounds__(256)
epilogue_kernel(const float* __restrict__ vi, const float* __restrict__ lambp)
{
    const int h  = blockIdx.x;
    const int t0 = blockIdx.y * 32;
    const int tid = threadIdx.x, warp = tid >> 5, lane = tid & 31;
    const float lamb = *lambp;

    __shared__ float vsh[64][33];

    const float invf = powf(1e-4f, (float)lane * (1.0f / 32.0f));

#pragma unroll
    for (int it = 0; it < 4; it++) {
        const int tl = warp * 4 + it;
        const int t  = t0 + tl;
        const int base = t * DMODEL + h * 64 + lane;

        float q1 = g_q[base], q2 = g_q[base + 32];
        float k1 = g_k[base], k2 = g_k[base + 32];
        float v1 = g_v[base], v2 = g_v[base + 32];
        float w1 = vi[base],  w2 = vi[base + 32];
        v1 = (1.f - lamb) * v1 + lamb * w1;
        v2 = (1.f - lamb) * v2 + lamb * w2;

        float sq = q1 * q1 + q2 * q2;
        float sk = k1 * k1 + k2 * k2;
#pragma unroll
        for (int m = 16; m; m >>= 1) {
            sq += __shfl_xor_sync(0xffffffffu, sq, m);
            sk += __shfl_xor_sync(0xffffffffu, sk, m);
        }
        const float rq = rsqrtf(sq * (1.f / 64.f) + 1.1920929e-7f);
        const float rk = rsqrtf(sk * (1.f / 64.f) + 1.1920929e-7f);
        q1 *= rq; q2 *= rq; k1 *= rk; k2 *= rk;

        const float ang = (float)t * invf;
        float s, c;
        sincosf(ang, &s, &c);
        float qa =  q1 * c + q2 * s;
        float qb = -q1 * s + q2 * c;
        float ka =  k1 * c + k2 * s;
        float kb = -k1 * s + k2 * c;

        qa *= 0.125f; qb *= 0.125f;

        const int ob = (h * SEQ + t) * 64 + lane;
        g_qb[ob]      = to_tf32(qa);
        g_qb[ob + 32] = to_tf32(qb);
        g_kb[ob]      = to_tf32(ka);
        g_kb[ob + 32] = to_tf32(kb);

        vsh[lane][tl]      = to_tf32(v1);
        vsh[lane + 32][tl] = to_tf32(v2);
    }
    __syncthreads();

#pragma unroll
    for (int v = 0; v < 8; v++) {
        int idx = tid + v * 256;
        int d = idx >> 5, tl = idx & 31;
        g_vt[(h * 64 + d) * SEQ + t0 + tl] = vsh[d][tl];
    }
}

// ---------------------------------------------------------------------------
// Kernel 3: causal flash attention with IN-CTA KV SPLIT (byte-exact R9 —
// the best-measured attention: 82.7 us).
// grid (32, 12), 256 threads = 8 warps; halves process disjoint KV ranges,
// exact online-softmax merge at the end. smem 87,040 B -> 2 CTAs/SM.
// ---------------------------------------------------------------------------
__global__ void __launch_bounds__(256, 2)
attn_kernel()
{
    extern __shared__ float sm_attn[];
    constexpr int TS = 64 * 68;
    float (*qs)[68] = (float(*)[68])(sm_attn);

    const int tid  = threadIdx.x;
    const int warp = tid >> 5, lane = tid & 31;
    const int half = warp >> 2, w = warp & 3;
    const int htid = tid & 127;

    float (*ks)[68] = (float(*)[68])(sm_attn + (1 + 2 * half) * TS);
    float (*vs)[68] = (float(*)[68])(sm_attn + (2 + 2 * half) * TS);
    float (*ps)[68] = ks;                     // alias: P overwrites consumed K
    const uint32_t qsb = smem_u32(sm_attn);
    const uint32_t ksb = smem_u32(&ks[0][0]);
    const uint32_t vsb = smem_u32(&vs[0][0]);
    // merge exchange buffers live in half-0's (dead-by-then) K/V regions
    float* xo  = sm_attn + 1 * TS;            // [128][33] floats
    float* xml = sm_attn + 2 * TS;            // [128][4]  floats

    const int bx = blockIdx.x;
    const int qt = (bx & 1) ? (bx >> 1) : (31 - (bx >> 1));
    const int h  = blockIdx.y;
    const int g = lane >> 2, t4 = lane & 3;

    const int nj  = qt + 1;
    const int c0  = nj >> 1;
    const int jlo = half ? c0 : 0;
    const int jhi = half ? nj : c0;

    const float* qg = g_qb + (h * SEQ + qt * 64) * 64;
    const float* kh = g_kb + h * SEQ * 64;
    const float* vh = g_vt + (h * 64) * SEQ;

    auto issue_kv = [&](int jt) {
#pragma unroll
        for (int v = 0; v < 8; v++) {
            int idx = htid + v * 128;
            int r = idx >> 4, c4 = idx & 15;
            cp_async16(ksb + (uint32_t)(r * 272 + c4 * 16),
                       kh + (jt * 64 + r) * 64 + c4 * 4);
            cp_async16(vsb + (uint32_t)(r * 272 + c4 * 16),
                       vh + r * SEQ + jt * 64 + c4 * 4);
        }
        cp_commit();
    };
    auto barh = [&]() {
        asm volatile("bar.sync %0, 128;" :: "r"(1 + half) : "memory");
    };

    // initial: Q (all 256 threads) + this half's first K/V
#pragma unroll
    for (int v = 0; v < 4; v++) {
        int idx = tid + v * 256;
        int r = idx >> 4, c4 = idx & 15;
        cp_async16(qsb + (uint32_t)(r * 272 + c4 * 16), qg + r * 64 + c4 * 4);
    }
    if (jhi > jlo) issue_kv(jlo);
    else           cp_commit();
    cp_wait<0>();
    __syncthreads();

    float o[8][4];
#pragma unroll
    for (int nt = 0; nt < 8; nt++)
#pragma unroll
        for (int e = 0; e < 4; e++) o[nt][e] = 0.f;
    float m0 = -INFINITY, m1 = -INFINITY, l0 = 0.f, l1 = 0.f;

    const int r0 = w * 16 + g;

    for (int jt = jlo; jt < jhi; jt++) {
        if (jt > jlo) cp_wait<0>();
        barh();

        // ---- S = Q K^T ----
        float s[8][4];
#pragma unroll
        for (int nt = 0; nt < 8; nt++)
#pragma unroll
            for (int e = 0; e < 4; e++) s[nt][e] = 0.f;
#pragma unroll
        for (int kk = 0; kk < 8; kk++) {
            float af[4];
            af[0] = qs[r0    ][kk * 8 + t4];
            af[1] = qs[r0 + 8][kk * 8 + t4];
            af[2] = qs[r0    ][kk * 8 + t4 + 4];
            af[3] = qs[r0 + 8][kk * 8 + t4 + 4];
#pragma unroll
            for (int nt = 0; nt < 8; nt++) {
                float bf[2];
                bf[0] = ks[nt * 8 + g][kk * 8 + t4];
                bf[1] = ks[nt * 8 + g][kk * 8 + t4 + 4];
                mma8(s[nt], af, bf);
            }
        }
        barh();                     // half done reading ks (P will overwrite)

        // ---- causal mask (diagonal tile; reachable only in upper half) ----
        if (jt == qt) {
#pragma unroll
            for (int nt = 0; nt < 8; nt++) {
                int cc = nt * 8 + 2 * t4;
                if (cc     > r0    ) s[nt][0] = -1e30f;
                if (cc + 1 > r0    ) s[nt][1] = -1e30f;
                if (cc     > r0 + 8) s[nt][2] = -1e30f;
                if (cc + 1 > r0 + 8) s[nt][3] = -1e30f;
            }
        }

        // ---- online softmax ----
        float mx0 = -INFINITY, mx1 = -INFINITY;
#pragma unroll
        for (int nt = 0; nt < 8; nt++) {
            mx0 = fmaxf(mx0, fmaxf(s[nt][0], s[nt][1]));
            mx1 = fmaxf(mx1, fmaxf(s[nt][2], s[nt][3]));
        }
        mx0 = red_max4(mx0);
        mx1 = red_max4(mx1);
        const float mn0 = fmaxf(m0, mx0), mn1 = fmaxf(m1, mx1);
        const float a0 = __expf(m0 - mn0), a1 = __expf(m1 - mn1);

        float rs0 = 0.f, rs1 = 0.f;
#pragma unroll
        for (int nt = 0; nt < 8; nt++) {
            s[nt][0] = __expf(s[nt][0] - mn0);
            s[nt][1] = __expf(s[nt][1] - mn0);
            s[nt][2] = __expf(s[nt][2] - mn1);
            s[nt][3] = __expf(s[nt][3] - mn1);
            rs0 += s[nt][0] + s[nt][1];
            rs1 += s[nt][2] + s[nt][3];
        }
        rs0 = red_sum4(rs0);
        rs1 = red_sum4(rs1);
        l0 = l0 * a0 + rs0;
        l1 = l1 * a1 + rs1;
#pragma unroll
        for (int nt = 0; nt < 8; nt++) {
            o[nt][0] *= a0; o[nt][1] *= a0;
            o[nt][2] *= a1; o[nt][3] *= a1;
        }
        m0 = mn0; m1 = mn1;

        // ---- P into (dead) K buffer; intra-warp 16-row band ----
#pragma unroll
        for (int nt = 0; nt < 8; nt++) {
            int cc = nt * 8 + 2 * t4;
            ps[r0    ][cc]     = to_tf32(s[nt][0]);
            ps[r0    ][cc + 1] = to_tf32(s[nt][1]);
            ps[r0 + 8][cc]     = to_tf32(s[nt][2]);
            ps[r0 + 8][cc + 1] = to_tf32(s[nt][3]);
        }
        __syncwarp();

        // ---- O += P @ V ----
#pragma unroll
        for (int kk = 0; kk < 8; kk++) {
            float af[4];
            af[0] = ps[r0    ][kk * 8 + t4];
            af[1] = ps[r0 + 8][kk * 8 + t4];
            af[2] = ps[r0    ][kk * 8 + t4 + 4];
            af[3] = ps[r0 + 8][kk * 8 + t4 + 4];
#pragma unroll
            for (int nt = 0; nt < 8; nt++) {
                float bf[2];
                bf[0] = vs[nt * 8 + g][kk * 8 + t4];
                bf[1] = vs[nt * 8 + g][kk * 8 + t4 + 4];
                mma8(o[nt], af, bf);
            }
        }
        barh();                     // done with vs + ps before next load
        if (jt + 1 < jhi) issue_kv(jt + 1);
    }

    // ---- merge halves (exact split-softmax recombination) ----
    if (half == 0) {
#pragma unroll
        for (int nt = 0; nt < 8; nt++) {
#pragma unroll
            for (int e = 0; e < 4; e++)
                xo[htid * 33 + nt * 4 + e] = o[nt][e];
        }
        xml[htid * 4 + 0] = m0;
        xml[htid * 4 + 1] = m1;
        xml[htid * 4 + 2] = l0;
        xml[htid * 4 + 3] = l1;
    }
    __syncthreads();
    if (half == 1) {
        const float mA0 = xml[htid * 4 + 0], mA1 = xml[htid * 4 + 1];
        const float lA0 = xml[htid * 4 + 2], lA1 = xml[htid * 4 + 3];
        const float ms0 = fmaxf(m0, mA0), ms1 = fmaxf(m1, mA1);
        const float aa0 = __expf(mA0 - ms0), bb0 = __expf(m0 - ms0);
        const float aa1 = __expf(mA1 - ms1), bb1 = __expf(m1 - ms1);
        const float il0 = 1.f / (aa0 * lA0 + bb0 * l0);
        const float il1 = 1.f / (aa1 * lA1 + bb1 * l1);

        const int tr0 = qt * 64 + r0;
#pragma unroll
        for (int nt = 0; nt < 8; nt++) {
            const float* xp = xo + htid * 33 + nt * 4;
            int col = h * 64 + nt * 8 + 2 * t4;
            float v0 = (aa0 * xp[0] + bb0 * o[nt][0]) * il0;
            float v1 = (aa0 * xp[1] + bb0 * o[nt][1]) * il0;
            float v2 = (aa1 * xp[2] + bb1 * o[nt][2]) * il1;
            float v3 = (aa1 * xp[3] + bb1 * o[nt][3]) * il1;
            *(float2*)(g_ob + tr0 * DMODEL + col) =
                make_float2(to_tf32(v0), to_tf32(v1));
            *(float2*)(g_ob + (tr0 + 8) * DMODEL + col) =
                make_float2(to_tf32(v2), to_tf32(v3));
        }
    }
}

// ---------------------------------------------------------------------------
// Launch
// ---------------------------------------------------------------------------
extern "C" void kernel_launch(void* const* d_in, const int* in_sizes, int n_in,
                              void* d_out, int out_size)
{
    (void)in_sizes; (void)n_in; (void)out_size;
    const float* x    = (const float*)d_in[0];
    const float* vi   = (const float*)d_in[1];
    const float* Wq   = (const float*)d_in[2];
    const float* Wk   = (const float*)d_in[3];
    const float* Wv   = (const float*)d_in[4];
    const float* Wp   = (const float*)d_in[5];
    const float* lamb = (const float*)d_in[6];

    cudaFuncSetAttribute(gemm_qkv_k,
                         cudaFuncAttributeMaxDynamicSharedMemorySize, QKV_SMEM);
    cudaFuncSetAttribute(gemm_proj_k,
                         cudaFuncAttributeMaxDynamicSharedMemorySize, PROJ_SMEM);

    round_kernel<<<3840, 256>>>(x, Wq, Wk, Wv, Wp);
    gemm_qkv_k<<<dim3(16, 18), 256, QKV_SMEM>>>();
    epilogue_kernel<<<dim3(12, 64), 256>>>(vi, lamb);

    const int attn_smem = 5 * 64 * 68 * (int)sizeof(float);  // 87040 B
    cudaFuncSetAttribute(attn_kernel, cudaFuncAttributeMaxDynamicSharedMemorySize,
                         attn_smem);
    attn_kernel<<<dim3(32, 12), 256, attn_smem>>>();

    gemm_proj_k<<<dim3(16, 12), 256, PROJ_SMEM>>>((float*)d_out);
}

// round 16
// speedup vs baseline: 1.2645x; 1.0978x over previous
#include <cuda_runtime.h>
#include <math.h>
#include <stdint.h>

static constexpr int SEQ    = 2048;
static constexpr int DMODEL = 768;
static constexpr int NHEAD  = 12;
static constexpr int HDIM   = 64;

// ---------------------------------------------------------------------------
// Scratch (no allocations allowed -> __device__ globals)
// ---------------------------------------------------------------------------
__device__ float g_xr [SEQ * DMODEL];           // tf32-rounded x
__device__ float g_wr [3 * DMODEL * DMODEL];    // tf32-rounded [Wq;Wk;Wv]
__device__ float g_wpr[DMODEL * DMODEL];        // tf32-rounded Wp
__device__ float g_q [SEQ * DMODEL];            // x @ Wq^T   (fp32)
__device__ float g_k [SEQ * DMODEL];            // x @ Wk^T
__device__ float g_v [SEQ * DMODEL];            // x @ Wv^T
__device__ float g_qb[NHEAD * SEQ * HDIM];      // normed+rope+scaled Q, [h][t][d], tf32
__device__ float g_kb[NHEAD * SEQ * HDIM];      // normed+rope K, [h][t][d], tf32
__device__ float g_vt[NHEAD * HDIM * SEQ];      // blended V^T, [h][d][t], tf32
__device__ float g_ob[SEQ * DMODEL];            // attention output, [t][h*64+d], tf32

// ---------------------------------------------------------------------------
// Helpers
// ---------------------------------------------------------------------------
__device__ __forceinline__ float to_tf32(float x) {
    uint32_t u;
    asm("cvt.rna.tf32.f32 %0, %1;" : "=r"(u) : "f"(x));
    return __uint_as_float(u);
}

__device__ __forceinline__ uint32_t smem_u32(const void* p) {
    uint32_t a;
    asm("{ .reg .u64 t; cvta.to.shared.u64 t, %1; cvt.u32.u64 %0, t; }"
        : "=r"(a) : "l"(p));
    return a;
}

__device__ __forceinline__ void cp_async16(uint32_t s, const void* g) {
    asm volatile("cp.async.cg.shared.global [%0], [%1], 16;" :: "r"(s), "l"(g));
}
__device__ __forceinline__ void cp_commit() {
    asm volatile("cp.async.commit_group;" ::: "memory");
}
template <int N>
__device__ __forceinline__ void cp_wait() {
    asm volatile("cp.async.wait_group %0;" :: "n"(N) : "memory");
}

// ldmatrix x4: loads 4 8x8 b16 matrices == one tf32 A-fragment (or two B frags)
__device__ __forceinline__ void ldsm4(uint32_t* r, uint32_t addr) {
    asm volatile("ldmatrix.sync.aligned.m8n8.x4.shared.b16 {%0,%1,%2,%3}, [%4];"
                 : "=r"(r[0]), "=r"(r[1]), "=r"(r[2]), "=r"(r[3]) : "r"(addr));
}

// D += A * B : m16n8k8 tf32 mma, uint-register operands.
__device__ __forceinline__ void mma8u(float* d, const uint32_t* a, const uint32_t* b) {
    asm volatile(
        "mma.sync.aligned.m16n8k8.row.col.f32.tf32.tf32.f32 "
        "{%0,%1,%2,%3}, {%4,%5,%6,%7}, {%8,%9}, {%0,%1,%2,%3};\n"
        : "+f"(d[0]), "+f"(d[1]), "+f"(d[2]), "+f"(d[3])
        : "r"(a[0]), "r"(a[1]), "r"(a[2]), "r"(a[3]), "r"(b[0]), "r"(b[1]));
}

__device__ __forceinline__ float red_max4(float v) {
    v = fmaxf(v, __shfl_xor_sync(0xffffffffu, v, 1));
    v = fmaxf(v, __shfl_xor_sync(0xffffffffu, v, 2));
    return v;
}
__device__ __forceinline__ float red_sum4(float v) {
    v += __shfl_xor_sync(0xffffffffu, v, 1);
    v += __shfl_xor_sync(0xffffffffu, v, 2);
    return v;
}

// ---------------------------------------------------------------------------
// Kernel 0: rna-tf32 pre-round of x and all weights (one float4 per thread)
// ---------------------------------------------------------------------------
__global__ void __launch_bounds__(256)
round_kernel(const float* __restrict__ x,  const float* __restrict__ wq,
             const float* __restrict__ wk, const float* __restrict__ wv,
             const float* __restrict__ wp)
{
    int i = blockIdx.x * 256 + threadIdx.x;  // float4 index, total 983040
    const float* src;
    float* dst;
    int off;
    if (i < 393216)       { src = x;  dst = g_xr;           off = i; }
    else if (i < 540672)  { src = wq; dst = g_wr;           off = i - 393216; }
    else if (i < 688128)  { src = wk; dst = g_wr + 589824;  off = i - 540672; }
    else if (i < 835584)  { src = wv; dst = g_wr + 1179648; off = i - 688128; }
    else                  { src = wp; dst = g_wpr;          off = i - 835584; }
    float4 v = ((const float4*)src)[off];
    v.x = to_tf32(v.x); v.y = to_tf32(v.y);
    v.z = to_tf32(v.z); v.w = to_tf32(v.w);
    ((float4*)dst)[off] = v;
}

// ---------------------------------------------------------------------------
// Templated tf32 mma.sync GEMM core: C[BM x BN] tile of A[*,768] @ B[*,768]^T.
// 3-stage cp.async pipeline, ONE __syncthreads per K-chunk.
// Fragment feeding via ldmatrix.x4 (1 issue per A-frag, 2 B-frags per issue).
// ---------------------------------------------------------------------------
template <int BM, int BN, int WGM, int WGN>
__device__ __forceinline__ void gemm_mma_core(const float* __restrict__ A,
                                              const float* __restrict__ B,
                                              float* __restrict__ C, int ldc)
{
    constexpr int MT = BM / WGM / 16;
    constexpr int NT = BN / WGN / 8;
    constexpr int NP = NT / 2;              // B ldmatrix pairs
    constexpr int NKT = DMODEL / 32;
    constexpr int ACH = BM / 32;
    constexpr int BCH = BN / 32;

    extern __shared__ float sm[];
    const uint32_t sb = smem_u32(sm);
    const uint32_t bReg = (uint32_t)(3 * BM * 144);   // byte offset of B region

    const int tid  = threadIdx.x;
    const int warp = tid >> 5, lane = tid & 31;
    const int wm = warp % WGM, wn = warp / WGM;
    const int g  = lane >> 2, t4 = lane & 3;
    const int l7 = lane & 7, lb3 = (lane >> 3) & 1, lb4 = (lane >> 4) & 1;

    // ldmatrix per-thread row bases (within tile, bytes added later)
    const int rowA0 = wm * (BM / WGM) + lb3 * 8 + l7;
    const int rowB0 = wn * (BN / WGN) + lb4 * 8 + l7;

    float acc[MT][NT][4];
#pragma unroll
    for (int i = 0; i < MT; i++)
#pragma unroll
        for (int j = 0; j < NT; j++)
#pragma unroll
            for (int e = 0; e < 4; e++) acc[i][j][e] = 0.f;

    auto issue = [&](int buf, int kt) {
        const uint32_t aO = (uint32_t)(buf * BM * 144);
        const uint32_t bO = bReg + (uint32_t)(buf * BN * 144);
        const float* ga = A + kt * 32;
#pragma unroll
        for (int v = 0; v < ACH; v++) {
            int idx = tid + v * 256, r = idx >> 3, c4 = idx & 7;
            cp_async16(sb + aO + (uint32_t)(r * 144 + c4 * 16),
                       ga + r * DMODEL + c4 * 4);
        }
        const float* gb = B + kt * 32;
#pragma unroll
        for (int v = 0; v < BCH; v++) {
            int idx = tid + v * 256, r = idx >> 3, c4 = idx & 7;
            cp_async16(sb + bO + (uint32_t)(r * 144 + c4 * 16),
                       gb + r * DMODEL + c4 * 4);
        }
        cp_commit();
    };

    issue(0, 0);
    issue(1, 1);

    for (int kt = 0; kt < NKT; kt++) {
        if (kt + 1 < NKT) cp_wait<1>();
        else              cp_wait<0>();
        __syncthreads();                    // chunk kt ready; all warps past kt-1
        if (kt + 2 < NKT) issue((kt + 2) % 3, kt + 2);

        const int buf = kt % 3;
        const uint32_t baseA = sb + (uint32_t)(buf * BM * 144)
                             + (uint32_t)(rowA0 * 144 + lb4 * 16);
        const uint32_t baseB = sb + bReg + (uint32_t)(buf * BN * 144)
                             + (uint32_t)(rowB0 * 144 + lb3 * 16);

#pragma unroll
        for (int kk = 0; kk < 4; kk++) {
            uint32_t af[MT][4];
#pragma unroll
            for (int mt = 0; mt < MT; mt++)
                ldsm4(af[mt], baseA + (uint32_t)(mt * 2304 + kk * 32));
#pragma unroll
            for (int p = 0; p < NP; p++) {
                uint32_t bb[4];
                ldsm4(bb, baseB + (uint32_t)(p * 2304 + kk * 32));
#pragma unroll
                for (int mt = 0; mt < MT; mt++) {
                    mma8u(acc[mt][2 * p],     af[mt], bb);
                    mma8u(acc[mt][2 * p + 1], af[mt], bb + 2);
                }
            }
        }
    }
    __syncthreads();

#pragma unroll
    for (int mt = 0; mt < MT; mt++) {
        int r0 = wm * (BM / WGM) + mt * 16 + g;
#pragma unroll
        for (int nt = 0; nt < NT; nt++) {
            int c0 = wn * (BN / WGN) + nt * 8 + 2 * t4;
            *(float2*)(C + r0 * ldc + c0)       = make_float2(acc[mt][nt][0], acc[mt][nt][1]);
            *(float2*)(C + (r0 + 8) * ldc + c0) = make_float2(acc[mt][nt][2], acc[mt][nt][3]);
        }
    }
}

static constexpr int QKV_SMEM  = 3 * (128 + 128) * 36 * 4;  // 110592
static constexpr int PROJ_SMEM = 3 * (128 +  64) * 36 * 4;  // 82944

// Kernel 1: fused QKV projection. grid (16, 18)
__global__ void __launch_bounds__(256, 2)
gemm_qkv_k()
{
    int bm = blockIdx.x;
    int nb = blockIdx.y;
    int sel = nb / 6, bn = nb % 6;
    float* Cbase = (sel == 0) ? g_q : (sel == 1) ? g_k : g_v;
    gemm_mma_core<128, 128, 2, 4>(g_xr + bm * 128 * DMODEL,
                                  g_wr + nb * 128 * DMODEL,
                                  Cbase + bm * 128 * DMODEL + bn * 128, DMODEL);
}

// Kernel 4: output projection. grid (16, 12)
__global__ void __launch_bounds__(256, 2)
gemm_proj_k(float* __restrict__ out)
{
    gemm_mma_core<128, 64, 4, 2>(g_ob + blockIdx.x * 128 * DMODEL,
                                 g_wpr + blockIdx.y * 64 * DMODEL,
                                 out + blockIdx.x * 128 * DMODEL + blockIdx.y * 64,
                                 DMODEL);
}

// ---------------------------------------------------------------------------
// Kernel 2: V blend + RMS-norm(q,k) + RoPE + layout shuffles.  grid (12, 64)
// (standard row-major layouts — ldmatrix needs no permutation)
// ---------------------------------------------------------------------------
__global__ void __launch_bounds__(256)
epilogue_kernel(const float* __restrict__ vi, const float* __restrict__ lambp)
{
    const int h  = blockIdx.x;
    const int t0 = blockIdx.y * 32;
    const int tid = threadIdx.x, warp = tid >> 5, lane = tid & 31;
    const float lamb = *lambp;

    __shared__ float vsh[64][33];

    const float invf = powf(1e-4f, (float)lane * (1.0f / 32.0f));

#pragma unroll
    for (int it = 0; it < 4; it++) {
        const int tl = warp * 4 + it;
        const int t  = t0 + tl;
        const int base = t * DMODEL + h * 64 + lane;

        float q1 = g_q[base], q2 = g_q[base + 32];
        float k1 = g_k[base], k2 = g_k[base + 32];
        float v1 = g_v[base], v2 = g_v[base + 32];
        float w1 = vi[base],  w2 = vi[base + 32];
        v1 = (1.f - lamb) * v1 + lamb * w1;
        v2 = (1.f - lamb) * v2 + lamb * w2;

        float sq = q1 * q1 + q2 * q2;
        float sk = k1 * k1 + k2 * k2;
#pragma unroll
        for (int m = 16; m; m >>= 1) {
            sq += __shfl_xor_sync(0xffffffffu, sq, m);
            sk += __shfl_xor_sync(0xffffffffu, sk, m);
        }
        const float rq = rsqrtf(sq * (1.f / 64.f) + 1.1920929e-7f);
        const float rk = rsqrtf(sk * (1.f / 64.f) + 1.1920929e-7f);
        q1 *= rq; q2 *= rq; k1 *= rk; k2 *= rk;

        const float ang = (float)t * invf;
        float s, c;
        sincosf(ang, &s, &c);
        float qa =  q1 * c + q2 * s;
        float qb = -q1 * s + q2 * c;
        float ka =  k1 * c + k2 * s;
        float kb = -k1 * s + k2 * c;

        qa *= 0.125f; qb *= 0.125f;

        const int ob = (h * SEQ + t) * 64 + lane;
        g_qb[ob]      = to_tf32(qa);
        g_qb[ob + 32] = to_tf32(qb);
        g_kb[ob]      = to_tf32(ka);
        g_kb[ob + 32] = to_tf32(kb);

        vsh[lane][tl]      = to_tf32(v1);
        vsh[lane + 32][tl] = to_tf32(v2);
    }
    __syncthreads();

#pragma unroll
    for (int v = 0; v < 8; v++) {
        int idx = tid + v * 256;
        int d = idx >> 5, tl = idx & 31;
        g_vt[(h * 64 + d) * SEQ + t0 + tl] = vsh[d][tl];
    }
}

// ---------------------------------------------------------------------------
// Kernel 3: causal flash attention, in-CTA KV split (R9 structure) with
// ldmatrix fragment feeding: 80 LDSM vs 320 LDS per warp-iter.
// grid (32, 12), 256 threads = 8 warps; smem 87,040 B -> 2 CTAs/SM.
// ---------------------------------------------------------------------------
__global__ void __launch_bounds__(256, 2)
attn_kernel()
{
    extern __shared__ float sm_attn[];
    constexpr int TS = 64 * 68;
    float (*qs)[68] = (float(*)[68])(sm_attn);

    const int tid  = threadIdx.x;
    const int warp = tid >> 5, lane = tid & 31;
    const int half = warp >> 2, w = warp & 3;
    const int htid = tid & 127;

    float (*ks)[68] = (float(*)[68])(sm_attn + (1 + 2 * half) * TS);
    float (*ps)[68] = ks;                     // alias: P overwrites consumed K
    const uint32_t qsb = smem_u32(sm_attn);
    const uint32_t ksb = smem_u32(&ks[0][0]);
    const uint32_t vsb = ksb + (uint32_t)(TS * 4);
    // merge exchange buffers live in half-0's (dead-by-then) K/V regions
    float* xo  = sm_attn + 1 * TS;            // [128][33] floats
    float* xml = sm_attn + 2 * TS;            // [128][4]  floats

    const int bx = blockIdx.x;
    const int qt = (bx & 1) ? (bx >> 1) : (31 - (bx >> 1));
    const int h  = blockIdx.y;
    const int g = lane >> 2, t4 = lane & 3;
    const int l7 = lane & 7, lb3 = (lane >> 3) & 1, lb4 = (lane >> 4) & 1;

    const int nj  = qt + 1;
    const int c0  = nj >> 1;
    const int jlo = half ? c0 : 0;
    const int jhi = half ? nj : c0;

    const float* qg = g_qb + (h * SEQ + qt * 64) * 64;
    const float* kh = g_kb + h * SEQ * 64;
    const float* vh = g_vt + (h * 64) * SEQ;

    auto issue_kv = [&](int jt) {
#pragma unroll
        for (int v = 0; v < 8; v++) {
            int idx = htid + v * 128;
            int r = idx >> 4, c4 = idx & 15;
            cp_async16(ksb + (uint32_t)(r * 272 + c4 * 16),
                       kh + (jt * 64 + r) * 64 + c4 * 4);
            cp_async16(vsb + (uint32_t)(r * 272 + c4 * 16),
                       vh + r * SEQ + jt * 64 + c4 * 4);
        }
        cp_commit();
    };
    auto barh = [&]() {
        asm volatile("bar.sync %0, 128;" :: "r"(1 + half) : "memory");
    };

    // ldmatrix per-thread addresses
    const uint32_t aQ = qsb + (uint32_t)((w * 16 + lb3 * 8 + l7) * 272 + lb4 * 16);
    const uint32_t pA = ksb + (uint32_t)((w * 16 + lb3 * 8 + l7) * 272 + lb4 * 16);
    const uint32_t kB = ksb + (uint32_t)((lb4 * 8 + l7) * 272 + lb3 * 16);
    const uint32_t vB = vsb + (uint32_t)((lb4 * 8 + l7) * 272 + lb3 * 16);

    // initial: Q (all 256 threads) + this half's first K/V
#pragma unroll
    for (int v = 0; v < 4; v++) {
        int idx = tid + v * 256;
        int r = idx >> 4, c4 = idx & 15;
        cp_async16(qsb + (uint32_t)(r * 272 + c4 * 16), qg + r * 64 + c4 * 4);
    }
    if (jhi > jlo) issue_kv(jlo);
    else           cp_commit();
    cp_wait<0>();
    __syncthreads();

    float o[8][4];
#pragma unroll
    for (int nt = 0; nt < 8; nt++)
#pragma unroll
        for (int e = 0; e < 4; e++) o[nt][e] = 0.f;
    float m0 = -INFINITY, m1 = -INFINITY, l0 = 0.f, l1 = 0.f;

    const int r0 = w * 16 + g;

    for (int jt = jlo; jt < jhi; jt++) {
        if (jt > jlo) cp_wait<0>();
        barh();

        // ---- S = Q K^T  (ldmatrix feeds) ----
        float s[8][4];
#pragma unroll
        for (int nt = 0; nt < 8; nt++)
#pragma unroll
            for (int e = 0; e < 4; e++) s[nt][e] = 0.f;
#pragma unroll
        for (int kk = 0; kk < 8; kk++) {
            uint32_t af[4];
            ldsm4(af, aQ + (uint32_t)(kk * 32));
#pragma unroll
            for (int p = 0; p < 4; p++) {
                uint32_t bb[4];
                ldsm4(bb, kB + (uint32_t)(p * 4352 + kk * 32));   // 4352 = 16*272
                mma8u(s[2 * p],     af, bb);
                mma8u(s[2 * p + 1], af, bb + 2);
            }
        }
        barh();                     // half done reading ks (P will overwrite)

        // ---- causal mask (diagonal tile; reachable only in upper half) ----
        if (jt == qt) {
#pragma unroll
            for (int nt = 0; nt < 8; nt++) {
                int cc = nt * 8 + 2 * t4;
                if (cc     > r0    ) s[nt][0] = -1e30f;
                if (cc + 1 > r0    ) s[nt][1] = -1e30f;
                if (cc     > r0 + 8) s[nt][2] = -1e30f;
                if (cc + 1 > r0 + 8) s[nt][3] = -1e30f;
            }
        }

        // ---- online softmax ----
        float mx0 = -INFINITY, mx1 = -INFINITY;
#pragma unroll
        for (int nt = 0; nt < 8; nt++) {
            mx0 = fmaxf(mx0, fmaxf(s[nt][0], s[nt][1]));
            mx1 = fmaxf(mx1, fmaxf(s[nt][2], s[nt][3]));
        }
        mx0 = red_max4(mx0);
        mx1 = red_max4(mx1);
        const float mn0 = fmaxf(m0, mx0), mn1 = fmaxf(m1, mx1);
        const float a0 = __expf(m0 - mn0), a1 = __expf(m1 - mn1);

        float rs0 = 0.f, rs1 = 0.f;
#pragma unroll
        for (int nt = 0; nt < 8; nt++) {
            s[nt][0] = __expf(s[nt][0] - mn0);
            s[nt][1] = __expf(s[nt][1] - mn0);
            s[nt][2] = __expf(s[nt][2] - mn1);
            s[nt][3] = __expf(s[nt][3] - mn1);
            rs0 += s[nt][0] + s[nt][1];
            rs1 += s[nt][2] + s[nt][3];
        }
        rs0 = red_sum4(rs0);
        rs1 = red_sum4(rs1);
        l0 = l0 * a0 + rs0;
        l1 = l1 * a1 + rs1;
#pragma unroll
        for (int nt = 0; nt < 8; nt++) {
            o[nt][0] *= a0; o[nt][1] *= a0;
            o[nt][2] *= a1; o[nt][3] *= a1;
        }
        m0 = mn0; m1 = mn1;

        // ---- P into (dead) K buffer; intra-warp 16-row band ----
#pragma unroll
        for (int nt = 0; nt < 8; nt++) {
            int cc = nt * 8 + 2 * t4;
            ps[r0    ][cc]     = to_tf32(s[nt][0]);
            ps[r0    ][cc + 1] = to_tf32(s[nt][1]);
            ps[r0 + 8][cc]     = to_tf32(s[nt][2]);
            ps[r0 + 8][cc + 1] = to_tf32(s[nt][3]);
        }
        __syncwarp();

        // ---- O += P @ V  (ldmatrix feeds) ----
#pragma unroll
        for (int kk = 0; kk < 8; kk++) {
            uint32_t af[4];
            ldsm4(af, pA + (uint32_t)(kk * 32));
#pragma unroll
            for (int p = 0; p < 4; p++) {
                uint32_t bb[4];
                ldsm4(bb, vB + (uint32_t)(p * 4352 + kk * 32));
                mma8u(o[2 * p],     af, bb);
                mma8u(o[2 * p + 1], af, bb + 2);
            }
        }
        barh();                     // done with vs + ps before next load
        if (jt + 1 < jhi) issue_kv(jt + 1);
    }

    // ---- merge halves (exact split-softmax recombination) ----
    if (half == 0) {
#pragma unroll
        for (int nt = 0; nt < 8; nt++) {
#pragma unroll
            for (int e = 0; e < 4; e++)
                xo[htid * 33 + nt * 4 + e] = o[nt][e];
        }
        xml[htid * 4 + 0] = m0;
        xml[htid * 4 + 1] = m1;
        xml[htid * 4 + 2] = l0;
        xml[htid * 4 + 3] = l1;
    }
    __syncthreads();
    if (half == 1) {
        const float mA0 = xml[htid * 4 + 0], mA1 = xml[htid * 4 + 1];
        const float lA0 = xml[htid * 4 + 2], lA1 = xml[htid * 4 + 3];
        const float ms0 = fmaxf(m0, mA0), ms1 = fmaxf(m1, mA1);
        const float aa0 = __expf(mA0 - ms0), bb0 = __expf(m0 - ms0);
        const float aa1 = __expf(mA1 - ms1), bb1 = __expf(m1 - ms1);
        const float il0 = 1.f / (aa0 * lA0 + bb0 * l0);
        const float il1 = 1.f / (aa1 * lA1 + bb1 * l1);

        const int tr0 = qt * 64 + r0;
#pragma unroll
        for (int nt = 0; nt < 8; nt++) {
            const float* xp = xo + htid * 33 + nt * 4;
            int col = h * 64 + nt * 8 + 2 * t4;
            float v0 = (aa0 * xp[0] + bb0 * o[nt][0]) * il0;
            float v1 = (aa0 * xp[1] + bb0 * o[nt][1]) * il0;
            float v2 = (aa1 * xp[2] + bb1 * o[nt][2]) * il1;
            float v3 = (aa1 * xp[3] + bb1 * o[nt][3]) * il1;
            *(float2*)(g_ob + tr0 * DMODEL + col) =
                make_float2(to_tf32(v0), to_tf32(v1));
            *(float2*)(g_ob + (tr0 + 8) * DMODEL + col) =
                make_float2(to_tf32(v2), to_tf32(v3));
        }
    }
}

// ---------------------------------------------------------------------------
// Launch
// ---------------------------------------------------------------------------
extern "C" void kernel_launch(void* const* d_in, const int* in_sizes, int n_in,
                              void* d_out, int out_size)
{
    (void)in_sizes; (void)n_in; (void)out_size;
    const float* x    = (const float*)d_in[0];
    const float* vi   = (const float*)d_in[1];
    const float* Wq   = (const float*)d_in[2];
    const float* Wk   = (const float*)d_in[3];
    const float* Wv   = (const float*)d_in[4];
    const float* Wp   = (const float*)d_in[5];
    const float* lamb = (const float*)d_in[6];

    cudaFuncSetAttribute(gemm_qkv_k,
                         cudaFuncAttributeMaxDynamicSharedMemorySize, QKV_SMEM);
    cudaFuncSetAttribute(gemm_proj_k,
                         cudaFuncAttributeMaxDynamicSharedMemorySize, PROJ_SMEM);

    round_kernel<<<3840, 256>>>(x, Wq, Wk, Wv, Wp);
    gemm_qkv_k<<<dim3(16, 18), 256, QKV_SMEM>>>();
    epilogue_kernel<<<dim3(12, 64), 256>>>(vi, lamb);

    const int attn_smem = 5 * 64 * 68 * (int)sizeof(float);  // 87040 B
    cudaFuncSetAttribute(attn_kernel, cudaFuncAttributeMaxDynamicSharedMemorySize,
                         attn_smem);
    attn_kernel<<<dim3(32, 12), 256, attn_smem>>>();

    gemm_proj_k<<<dim3(16, 12), 256, PROJ_SMEM>>>((float*)d_out);
}